// round 15
// baseline (speedup 1.0000x reference)
#include <cuda_runtime.h>
#include <cuda_bf16.h>
#include <cstdint>

// EDMLoss = mean((Xhat-X)^2) + 0.25*memloss - 0.1*mean(Dhat)
// memloss = 2*(sum||h||^2 + sum_row min_k(||m_k||^2 - 2 h.m_k)) / (B*D*T)
// SINGLE LAUNCH, 148 CTAs:
//   0..127  : GEMM CTAs (256 rows x 512 cols, mma.sync bf16). A-staging is
//             software-pipelined against chunk-0 MMA (16 segments of 16 d-rows,
//             register double-buffered LDGs in flight across barriers).
//   128..143: convert M->bf16 + ||m||^2, signal ready, then rec slices.
//   144..145: rec slices.   146..147: dhat slices.
// Ticketed finalize; all globals reset each run (graph-replay invariant).

namespace {
constexpr int Bn = 64, Dn = 256, Tn = 512, Kn = 512;
constexpr int N_REC  = 64 * 8 * 512;
constexpr int N_DHAT = 64 * 512;

constexpr uint32_t AP    = 528;                 // A pitch bytes (256 bf16 + 16 pad)
constexpr uint32_t BP    = 144;                 // B pitch bytes (64 bf16 + 16 pad)
constexpr uint32_t SA    = 0;                   // A: 256*528 = 135168
constexpr uint32_t SB0   = 135168;              // B buf0: 256*144 = 36864
constexpr uint32_t SB1   = 172032;              // B buf1
constexpr uint32_t SMNS  = 208896;              // 512 f32 ||m||^2
constexpr uint32_t SRMIN = 210944;              // 2 groups * 256 f32 row mins
constexpr uint32_t SRED  = 212992;              // 8 f32 | 8 doubles at +64
constexpr uint32_t SMEMT = 213120;
}

__device__ double g_acc[4];      // 0 rec, 1 minscore, 2 dhat, 3 sum H^2 (zero-invariant)
__device__ unsigned g_ticket;
__device__ unsigned g_mready;    // 16 converter CTAs arrive; reset by finalize
__device__ float  g_mnorm[Kn];
__device__ __align__(16) __nv_bfloat16 g_Mc[(size_t)Dn * Kn];

__device__ __forceinline__ uint32_t smem_u32(const void* p) {
    uint32_t a;
    asm("{ .reg .u64 t; cvta.to.shared.u64 t, %1; cvt.u32.u64 %0, t; }" : "=r"(a) : "l"(p));
    return a;
}
__device__ __forceinline__ void ldsm4t(uint32_t* r, uint32_t addr) {
    asm volatile("ldmatrix.sync.aligned.m8n8.x4.trans.shared.b16 {%0,%1,%2,%3}, [%4];"
                 : "=r"(r[0]), "=r"(r[1]), "=r"(r[2]), "=r"(r[3]) : "r"(addr));
}
__device__ __forceinline__ void mma16816(float* c, const uint32_t* a, const uint32_t* b) {
    asm volatile("mma.sync.aligned.m16n8k16.row.col.f32.bf16.bf16.f32 "
                 "{%0,%1,%2,%3}, {%4,%5,%6,%7}, {%8,%9}, {%0,%1,%2,%3};"
                 : "+f"(c[0]), "+f"(c[1]), "+f"(c[2]), "+f"(c[3])
                 : "r"(a[0]), "r"(a[1]), "r"(a[2]), "r"(a[3]), "r"(b[0]), "r"(b[1]));
}

__global__ __launch_bounds__(256, 1) void k_fused(const float* __restrict__ H,
                                                  const float* __restrict__ M,
                                                  const float* __restrict__ Xhat,
                                                  const float* __restrict__ X,
                                                  const float* __restrict__ Dh,
                                                  float* out) {
    extern __shared__ char sm[];
    const uint32_t sb = smem_u32(sm);
    const int tid = threadIdx.x, w = tid >> 5, ln = tid & 31;

    if (blockIdx.x >= 128) {
        // -------- converter / reduction CTAs --------
        if (blockIdx.x < 144) {
            __shared__ float part[8][32];
            const int kl = tid & 31, dg = tid >> 5;
            const int k  = ((int)blockIdx.x - 128) * 32 + kl;
            float s = 0.f;
            #pragma unroll 8
            for (int i = 0; i < 32; ++i) {
                int d = dg * 32 + i;
                float v = M[(size_t)d * Kn + k];
                g_Mc[(size_t)d * Kn + k] = __float2bfloat16(v);
                s = fmaf(v, v, s);
            }
            part[dg][kl] = s;
            __syncthreads();
            if (dg == 0) {
                float t = 0.f;
                #pragma unroll
                for (int i = 0; i < 8; ++i) t += part[i][kl];
                g_mnorm[k] = t;
            }
            __syncthreads();
            __threadfence();
            if (tid == 0) atomicAdd(&g_mready, 1u);
        }
        int which, n, b0, nb;
        const float* a; const float* bp;
        if (blockIdx.x < 146) { which = 0; a = Xhat; bp = X; n = N_REC;  b0 = 128; nb = 18; }
        else                  { which = 2; a = Dh;   bp = 0; n = N_DHAT; b0 = 146; nb = 2;  }
        float s = 0.f;
        for (int i = ((int)blockIdx.x - b0) * 256 + tid; i < n; i += nb * 256) {
            if (which == 0) { float d = a[i] - bp[i]; s = fmaf(d, d, s); }
            else            { s += a[i]; }
        }
        #pragma unroll
        for (int o = 16; o; o >>= 1) s += __shfl_down_sync(0xffffffffu, s, o);
        float* ws = (float*)(sm + SRED);
        if (!ln) ws[w] = s;
        __syncthreads();
        if (tid == 0) {
            float t = 0.f;
            #pragma unroll
            for (int i = 0; i < 8; ++i) t += ws[i];
            atomicAdd(&g_acc[which], (double)t);
        }
    } else {
        // -------- GEMM CTA: 256 rows x 512 cols --------
        const int row0 = blockIdx.x * 256;
        const int b = row0 >> 9, t0 = row0 & 511;          // t0 in {0, 256}
        const float* Hp = H + (size_t)b * Dn * Tn + t0;
        const int dofs = tid >> 6;                         // 0..3
        const int seg  = tid & 63;                         // float4 column group

        // A staging helpers: segment s covers d = [16s, 16s+15];
        // per thread 4 float4 loads (iters 4s..4s+3, d = dofs + 4*iter).
        float sq = 0.f;
        float4 bufA[4], bufB[4];
        auto issue = [&](int s, float4* buf) {
            #pragma unroll
            for (int j = 0; j < 4; ++j) {
                int d = dofs + 4 * (s * 4 + j);
                buf[j] = __ldg((const float4*)(Hp + (size_t)d * Tn + seg * 4));
            }
        };
        auto store = [&](int s, const float4* buf) {
            #pragma unroll
            for (int j = 0; j < 4; ++j) {
                int d = dofs + 4 * (s * 4 + j);
                float4 v = buf[j];
                sq = fmaf(v.x, v.x, fmaf(v.y, v.y, fmaf(v.z, v.z, fmaf(v.w, v.w, sq))));
                __nv_bfloat162 p0 = __floats2bfloat162_rn(v.x, v.y);
                __nv_bfloat162 p1 = __floats2bfloat162_rn(v.z, v.w);
                uint32_t a = sb + SA + d * AP + seg * 8;
                asm volatile("st.shared.v2.b32 [%0], {%1,%2};"
                             :: "r"(a), "r"(*(uint32_t*)&p0), "r"(*(uint32_t*)&p1) : "memory");
            }
        };

        issue(0, bufA);                                    // first DRAM batch in flight

        if (tid == 0)                                      // M conversion ready?
            while (*((volatile unsigned*)&g_mready) < 16u) __nanosleep(64);
        __syncthreads();
        __threadfence();

        ((float*)(sm + SMNS))[tid]       = g_mnorm[tid];
        ((float*)(sm + SMNS))[tid + 256] = g_mnorm[tid + 256];

        const size_t gmc = __cvta_generic_to_global((const void*)g_Mc);
        auto cp_chunk = [&](int c, uint32_t dstoff) {       // 64-col chunk: 256 rows * 128B
            #pragma unroll
            for (int i = 0; i < 8; ++i) {
                int u = tid + 256 * i;
                int d = u >> 3, sg = u & 7;
                uint32_t dst = sb + dstoff + d * BP + sg * 16;
                size_t   src = gmc + (size_t)d * 1024 + (size_t)c * 128 + sg * 16;
                asm volatile("cp.async.cg.shared.global [%0], [%1], 16;" :: "r"(dst), "l"(src));
            }
            asm volatile("cp.async.commit_group;" ::: "memory");
        };
        cp_chunk(0, SB0);
        cp_chunk(1, SB1);

        issue(1, bufB);
        store(0, bufA);
        __syncthreads();                                   // segment 0 visible

        const int wm  = (w & 3) * 64;
        const int wn  = (w >> 2) * 32;
        const int s1  = ((ln >> 3) & 1) * 8;
        const int s2  = (ln >> 4) * 8;
        const int r8  = ln & 7;
        const float* mns = (const float*)(sm + SMNS);

        float rm[8];
        #pragma unroll
        for (int i = 0; i < 8; ++i) rm[i] = 3.4e38f;

        // ---- chunk 0, pipelined against A staging ----
        float acc[4][4][4];
        #pragma unroll
        for (int mf = 0; mf < 4; ++mf)
            #pragma unroll
            for (int nf = 0; nf < 4; ++nf)
                #pragma unroll
                for (int j = 0; j < 4; ++j) acc[mf][nf][j] = 0.f;

        auto mma_step = [&](int ks, uint32_t bb) {
            const int d0 = ks * 16;
            uint32_t af[4][4], bf[2][4];
            #pragma unroll
            for (int np = 0; np < 2; ++np)
                ldsm4t(bf[np], bb + (d0 + s1 + r8) * BP + (wn + np * 16 + s2) * 2);
            #pragma unroll
            for (int mf = 0; mf < 4; ++mf)
                ldsm4t(af[mf], sb + SA + (d0 + s2 + r8) * AP + (wm + mf * 16 + s1) * 2);
            #pragma unroll
            for (int mf = 0; mf < 4; ++mf)
                #pragma unroll
                for (int nf = 0; nf < 4; ++nf)
                    mma16816(acc[mf][nf], af[mf], &bf[nf >> 1][(nf & 1) * 2]);
        };
        auto epilogue = [&](int c) {
            const int cb = c * 64 + wn + 2 * (ln & 3);
            #pragma unroll
            for (int nf = 0; nf < 4; ++nf) {
                float m0 = mns[cb + nf * 8], m1 = mns[cb + nf * 8 + 1];
                #pragma unroll
                for (int mf = 0; mf < 4; ++mf) {
                    rm[mf * 2]     = fminf(rm[mf * 2],
                        fminf(fmaf(-2.f, acc[mf][nf][0], m0), fmaf(-2.f, acc[mf][nf][1], m1)));
                    rm[mf * 2 + 1] = fminf(rm[mf * 2 + 1],
                        fminf(fmaf(-2.f, acc[mf][nf][2], m0), fmaf(-2.f, acc[mf][nf][3], m1)));
                }
            }
        };

        #pragma unroll 1
        for (int s = 1; s < 16; ++s) {
            if (s + 1 < 16) issue(s + 1, ((s + 1) & 1) ? bufB : bufA);
            store(s, (s & 1) ? bufB : bufA);
            if (s == 1) asm volatile("cp.async.wait_group 1;" ::: "memory");  // B0 resident
            __syncthreads();                               // segment s visible
            mma_step(s - 1, sb + SB0);                     // chunk 0, ks = s-1
        }
        mma_step(15, sb + SB0);
        epilogue(0);

        // ---- chunks 1..7 (steady state) ----
        #pragma unroll 1
        for (int c = 1; c < 8; ++c) {
            asm volatile("cp.async.wait_group 0;" ::: "memory");
            __syncthreads();                               // chunk c resident; c-1 consumers done
            if (c + 1 < 8) cp_chunk(c + 1, ((c + 1) & 1) ? SB1 : SB0);
            const uint32_t bb = sb + ((c & 1) ? SB1 : SB0);

            #pragma unroll
            for (int mf = 0; mf < 4; ++mf)
                #pragma unroll
                for (int nf = 0; nf < 4; ++nf)
                    #pragma unroll
                    for (int j = 0; j < 4; ++j) acc[mf][nf][j] = 0.f;

            #pragma unroll
            for (int ks = 0; ks < 16; ++ks) mma_step(ks, bb);
            epilogue(c);
        }

        // ---- reductions ----
        #pragma unroll
        for (int o = 16; o; o >>= 1) sq += __shfl_down_sync(0xffffffffu, sq, o);
        if (!ln) ((float*)(sm + SRED))[w] = sq;

        #pragma unroll
        for (int o = 1; o < 4; o <<= 1) {
            #pragma unroll
            for (int i = 0; i < 8; ++i) rm[i] = fminf(rm[i], __shfl_xor_sync(0xffffffffu, rm[i], o));
        }
        if ((ln & 3) == 0) {
            float* rmin = (float*)(sm + SRMIN) + (w >> 2) * 256;
            int r = wm + (ln >> 2);
            #pragma unroll
            for (int mf = 0; mf < 4; ++mf) {
                rmin[r + mf * 16]     = rm[mf * 2];
                rmin[r + mf * 16 + 8] = rm[mf * 2 + 1];
            }
        }
        __syncthreads();

        {   // combine n-groups, sum rows
            const float* r0 = (const float*)(sm + SRMIN);
            double s = (double)fminf(r0[tid], r0[tid + 256]);
            #pragma unroll
            for (int o = 16; o; o >>= 1) s += __shfl_down_sync(0xffffffffu, s, o);
            if (!ln) ((double*)(sm + SRED + 64))[w] = s;
        }
        __syncthreads();

        if (tid == 0) {
            const double* dr = (const double*)(sm + SRED + 64);
            double ms = 0.0;
            #pragma unroll
            for (int i = 0; i < 8; ++i) ms += dr[i];
            atomicAdd(&g_acc[1], ms);
            const float* hws = (const float*)(sm + SRED);
            double hs = 0.0;
            #pragma unroll
            for (int i = 0; i < 8; ++i) hs += (double)hws[i];
            atomicAdd(&g_acc[3], hs);
        }
    }

    // -------- shared ticketed finalize (all 148 CTAs) --------
    if (tid == 0) {
        __threadfence();
        unsigned old = atomicAdd(&g_ticket, 1u);
        if (old == gridDim.x - 1) {
            __threadfence();
            double a0 = *(volatile double*)&g_acc[0];
            double a1 = *(volatile double*)&g_acc[1];
            double a2 = *(volatile double*)&g_acc[2];
            double a3 = *(volatile double*)&g_acc[3];
            double mem = 2.0 * (a3 + a1) / (double)((size_t)Bn * Dn * Tn);
            out[0] = (float)(a0 / (double)N_REC + 0.25 * mem - 0.1 * a2 / (double)N_DHAT);
            g_acc[0] = 0.0; g_acc[1] = 0.0; g_acc[2] = 0.0; g_acc[3] = 0.0;
            g_ticket = 0u; g_mready = 0u;
            __threadfence();
        }
    }
}

extern "C" void kernel_launch(void* const* d_in, const int* in_sizes, int n_in,
                              void* d_out, int out_size) {
    (void)in_sizes; (void)n_in; (void)out_size;
    const float* Xhat = (const float*)d_in[0];
    const float* X    = (const float*)d_in[1];
    const float* H    = (const float*)d_in[2];
    const float* M    = (const float*)d_in[3];
    const float* Dh   = (const float*)d_in[4];

    cudaFuncSetAttribute(k_fused, cudaFuncAttributeMaxDynamicSharedMemorySize, SMEMT);

    k_fused<<<148, 256, SMEMT>>>(H, M, Xhat, X, Dh, (float*)d_out);
}

// round 16
// speedup vs baseline: 1.1105x; 1.1105x over previous
#include <cuda_runtime.h>
#include <cuda_bf16.h>
#include <cstdint>

// EDMLoss = mean((Xhat-X)^2) + 0.25*memloss - 0.1*mean(Dhat)
// memloss = 2*(sum||h||^2 + sum_row min_k(||m_k||^2 - 2 h.m_k)) / (B*D*T)
// SINGLE LAUNCH, 148 CTAs (R14 structure):
//   0..127  : GEMM CTAs (256 rows x 512 cols, mma.sync bf16 at the legacy-path
//             ceiling). A-staging split in halves; m-ready wait + B prefetch
//             issued between halves so the B0 flight hides under staging.
//   128..143: convert M->bf16 + ||m||^2, signal ready, then rec slices.
//   144..145: rec slices.   146..147: dhat slices.
// Ticketed finalize; all globals reset each run (graph-replay invariant).

namespace {
constexpr int Bn = 64, Dn = 256, Tn = 512, Kn = 512;
constexpr int N_REC  = 64 * 8 * 512;
constexpr int N_DHAT = 64 * 512;

constexpr uint32_t AP    = 528;                 // A pitch bytes (256 bf16 + 16 pad)
constexpr uint32_t BP    = 144;                 // B pitch bytes (64 bf16 + 16 pad)
constexpr uint32_t SA    = 0;                   // A: 256*528 = 135168
constexpr uint32_t SB0   = 135168;              // B buf0: 256*144 = 36864
constexpr uint32_t SB1   = 172032;              // B buf1
constexpr uint32_t SMNS  = 208896;              // 512 f32 ||m||^2
constexpr uint32_t SRMIN = 210944;              // 2 groups * 256 f32 row mins
constexpr uint32_t SRED  = 212992;              // 8 f32 | 8 doubles at +64
constexpr uint32_t SMEMT = 213120;
}

__device__ double g_acc[4];      // 0 rec, 1 minscore, 2 dhat, 3 sum H^2 (zero-invariant)
__device__ unsigned g_ticket;
__device__ unsigned g_mready;    // 16 converter CTAs arrive; reset by finalize
__device__ float  g_mnorm[Kn];
__device__ __align__(16) __nv_bfloat16 g_Mc[(size_t)Dn * Kn];

__device__ __forceinline__ uint32_t smem_u32(const void* p) {
    uint32_t a;
    asm("{ .reg .u64 t; cvta.to.shared.u64 t, %1; cvt.u32.u64 %0, t; }" : "=r"(a) : "l"(p));
    return a;
}
__device__ __forceinline__ void ldsm4t(uint32_t* r, uint32_t addr) {
    asm volatile("ldmatrix.sync.aligned.m8n8.x4.trans.shared.b16 {%0,%1,%2,%3}, [%4];"
                 : "=r"(r[0]), "=r"(r[1]), "=r"(r[2]), "=r"(r[3]) : "r"(addr));
}
__device__ __forceinline__ void mma16816(float* c, const uint32_t* a, const uint32_t* b) {
    asm volatile("mma.sync.aligned.m16n8k16.row.col.f32.bf16.bf16.f32 "
                 "{%0,%1,%2,%3}, {%4,%5,%6,%7}, {%8,%9}, {%0,%1,%2,%3};"
                 : "+f"(c[0]), "+f"(c[1]), "+f"(c[2]), "+f"(c[3])
                 : "r"(a[0]), "r"(a[1]), "r"(a[2]), "r"(a[3]), "r"(b[0]), "r"(b[1]));
}

__global__ __launch_bounds__(256, 1) void k_fused(const float* __restrict__ H,
                                                  const float* __restrict__ M,
                                                  const float* __restrict__ Xhat,
                                                  const float* __restrict__ X,
                                                  const float* __restrict__ Dh,
                                                  float* out) {
    extern __shared__ char sm[];
    const uint32_t sb = smem_u32(sm);
    const int tid = threadIdx.x, w = tid >> 5, ln = tid & 31;

    if (blockIdx.x >= 128) {
        // -------- converter / reduction CTAs --------
        if (blockIdx.x < 144) {
            __shared__ float part[8][32];
            const int kl = tid & 31, dg = tid >> 5;
            const int k  = ((int)blockIdx.x - 128) * 32 + kl;
            float s = 0.f;
            #pragma unroll 8
            for (int i = 0; i < 32; ++i) {
                int d = dg * 32 + i;
                float v = M[(size_t)d * Kn + k];
                g_Mc[(size_t)d * Kn + k] = __float2bfloat16(v);
                s = fmaf(v, v, s);
            }
            part[dg][kl] = s;
            __syncthreads();
            if (dg == 0) {
                float t = 0.f;
                #pragma unroll
                for (int i = 0; i < 8; ++i) t += part[i][kl];
                g_mnorm[k] = t;
            }
            __syncthreads();
            __threadfence();
            if (tid == 0) atomicAdd(&g_mready, 1u);
        }
        int which, n, b0, nb;
        const float* a; const float* bp;
        if (blockIdx.x < 146) { which = 0; a = Xhat; bp = X; n = N_REC;  b0 = 128; nb = 18; }
        else                  { which = 2; a = Dh;   bp = 0; n = N_DHAT; b0 = 146; nb = 2;  }
        float s = 0.f;
        for (int i = ((int)blockIdx.x - b0) * 256 + tid; i < n; i += nb * 256) {
            if (which == 0) { float d = a[i] - bp[i]; s = fmaf(d, d, s); }
            else            { s += a[i]; }
        }
        #pragma unroll
        for (int o = 16; o; o >>= 1) s += __shfl_down_sync(0xffffffffu, s, o);
        float* ws = (float*)(sm + SRED);
        if (!ln) ws[w] = s;
        __syncthreads();
        if (tid == 0) {
            float t = 0.f;
            #pragma unroll
            for (int i = 0; i < 8; ++i) t += ws[i];
            atomicAdd(&g_acc[which], (double)t);
        }
    } else {
        // -------- GEMM CTA: 256 rows x 512 cols --------
        const int row0 = blockIdx.x * 256;
        const int b = row0 >> 9, t0 = row0 & 511;          // t0 in {0, 256}
        const float* Hp = H + (size_t)b * Dn * Tn + t0;
        float sq = 0.f;

        auto stage_half = [&](int i0, int i1) {            // iters cover d = i*4 range
            #pragma unroll
            for (int i = i0; i < i1; ++i) {
                int u = tid + 256 * i;                     // float4 units
                int d = u >> 6, seg = u & 63;
                float4 v = *(const float4*)(Hp + (size_t)d * Tn + seg * 4);
                sq = fmaf(v.x, v.x, fmaf(v.y, v.y, fmaf(v.z, v.z, fmaf(v.w, v.w, sq))));
                __nv_bfloat162 p0 = __floats2bfloat162_rn(v.x, v.y);
                __nv_bfloat162 p1 = __floats2bfloat162_rn(v.z, v.w);
                uint32_t a = sb + SA + d * AP + seg * 8;
                asm volatile("st.shared.v2.b32 [%0], {%1,%2};"
                             :: "r"(a), "r"(*(uint32_t*)&p0), "r"(*(uint32_t*)&p1) : "memory");
            }
        };

        // half 1: d 0..127 (~2.5 us, well past the ~1 us M conversion)
        stage_half(0, 32);

        // m-ready sync + B prefetch issued NOW; flight hides under half 2
        if (tid == 0)
            while (*((volatile unsigned*)&g_mready) < 16u) __nanosleep(64);
        __syncthreads();
        __threadfence();

        ((float*)(sm + SMNS))[tid]       = g_mnorm[tid];
        ((float*)(sm + SMNS))[tid + 256] = g_mnorm[tid + 256];

        const size_t gmc = __cvta_generic_to_global((const void*)g_Mc);
        auto cp_chunk = [&](int c, uint32_t dstoff) {       // 64-col chunk: 256 rows * 128B
            #pragma unroll
            for (int i = 0; i < 8; ++i) {
                int u = tid + 256 * i;
                int d = u >> 3, sg = u & 7;
                uint32_t dst = sb + dstoff + d * BP + sg * 16;
                size_t   src = gmc + (size_t)d * 1024 + (size_t)c * 128 + sg * 16;
                asm volatile("cp.async.cg.shared.global [%0], [%1], 16;" :: "r"(dst), "l"(src));
            }
            asm volatile("cp.async.commit_group;" ::: "memory");
        };
        cp_chunk(0, SB0);
        cp_chunk(1, SB1);

        // half 2: d 128..255 (covers B0/B1 flight)
        stage_half(32, 64);

        #pragma unroll
        for (int o = 16; o; o >>= 1) sq += __shfl_down_sync(0xffffffffu, sq, o);
        if (!ln) ((float*)(sm + SRED))[w] = sq;
        __syncthreads();                                   // A fully staged + sq visible
        if (tid == 0) {
            const float* hws = (const float*)(sm + SRED);
            double hs = 0.0;
            #pragma unroll
            for (int i = 0; i < 8; ++i) hs += (double)hws[i];
            atomicAdd(&g_acc[3], hs);
        }

        // 8 warps: 4 (m) x 2 (n). Warp tile per chunk: 64 rows x 32 cols.
        const int wm  = (w & 3) * 64;
        const int wn  = (w >> 2) * 32;
        const int s1  = ((ln >> 3) & 1) * 8;
        const int s2  = (ln >> 4) * 8;
        const int r8  = ln & 7;
        const float* mns = (const float*)(sm + SMNS);

        float rm[8];
        #pragma unroll
        for (int i = 0; i < 8; ++i) rm[i] = 3.4e38f;

        // Single barrier per chunk (proven R13 pipeline).
        for (int c = 0; c < 8; ++c) {
            if (c == 0) asm volatile("cp.async.wait_group 1;" ::: "memory");
            else        asm volatile("cp.async.wait_group 0;" ::: "memory");
            __syncthreads();
            if (c >= 1 && c + 1 < 8) cp_chunk(c + 1, ((c + 1) & 1) ? SB1 : SB0);
            const uint32_t bb = sb + ((c & 1) ? SB1 : SB0);

            float acc[4][4][4];
            #pragma unroll
            for (int mf = 0; mf < 4; ++mf)
                #pragma unroll
                for (int nf = 0; nf < 4; ++nf)
                    #pragma unroll
                    for (int j = 0; j < 4; ++j) acc[mf][nf][j] = 0.f;

            #pragma unroll
            for (int ks = 0; ks < 16; ++ks) {
                const int d0 = ks * 16;
                uint32_t af[4][4], bf[2][4];
                #pragma unroll
                for (int np = 0; np < 2; ++np)
                    ldsm4t(bf[np], bb + (d0 + s1 + r8) * BP + (wn + np * 16 + s2) * 2);
                #pragma unroll
                for (int mf = 0; mf < 4; ++mf)
                    ldsm4t(af[mf], sb + SA + (d0 + s2 + r8) * AP + (wm + mf * 16 + s1) * 2);
                #pragma unroll
                for (int mf = 0; mf < 4; ++mf)
                    #pragma unroll
                    for (int nf = 0; nf < 4; ++nf)
                        mma16816(acc[mf][nf], af[mf], &bf[nf >> 1][(nf & 1) * 2]);
            }

            // epilogue: score = ||m||^2 - 2*dot, running min per row
            const int cb = c * 64 + wn + 2 * (ln & 3);
            #pragma unroll
            for (int nf = 0; nf < 4; ++nf) {
                float m0 = mns[cb + nf * 8], m1 = mns[cb + nf * 8 + 1];
                #pragma unroll
                for (int mf = 0; mf < 4; ++mf) {
                    rm[mf * 2]     = fminf(rm[mf * 2],
                        fminf(fmaf(-2.f, acc[mf][nf][0], m0), fmaf(-2.f, acc[mf][nf][1], m1)));
                    rm[mf * 2 + 1] = fminf(rm[mf * 2 + 1],
                        fminf(fmaf(-2.f, acc[mf][nf][2], m0), fmaf(-2.f, acc[mf][nf][3], m1)));
                }
            }
        }

        // combine 4 lanes sharing each row
        #pragma unroll
        for (int o = 1; o < 4; o <<= 1) {
            #pragma unroll
            for (int i = 0; i < 8; ++i) rm[i] = fminf(rm[i], __shfl_xor_sync(0xffffffffu, rm[i], o));
        }
        if ((ln & 3) == 0) {
            float* rmin = (float*)(sm + SRMIN) + (w >> 2) * 256;
            int r = wm + (ln >> 2);
            #pragma unroll
            for (int mf = 0; mf < 4; ++mf) {
                rmin[r + mf * 16]     = rm[mf * 2];
                rmin[r + mf * 16 + 8] = rm[mf * 2 + 1];
            }
        }
        __syncthreads();

        {   // combine n-groups, sum rows
            const float* r0 = (const float*)(sm + SRMIN);
            double s = (double)fminf(r0[tid], r0[tid + 256]);
            #pragma unroll
            for (int o = 16; o; o >>= 1) s += __shfl_down_sync(0xffffffffu, s, o);
            if (!ln) ((double*)(sm + SRED + 64))[w] = s;
        }
        __syncthreads();

        if (tid == 0) {
            const double* dr = (const double*)(sm + SRED + 64);
            double ms = 0.0;
            #pragma unroll
            for (int i = 0; i < 8; ++i) ms += dr[i];
            atomicAdd(&g_acc[1], ms);
        }
    }

    // -------- shared ticketed finalize (all 148 CTAs) --------
    if (tid == 0) {
        __threadfence();
        unsigned old = atomicAdd(&g_ticket, 1u);
        if (old == gridDim.x - 1) {
            __threadfence();
            double a0 = *(volatile double*)&g_acc[0];
            double a1 = *(volatile double*)&g_acc[1];
            double a2 = *(volatile double*)&g_acc[2];
            double a3 = *(volatile double*)&g_acc[3];
            double mem = 2.0 * (a3 + a1) / (double)((size_t)Bn * Dn * Tn);
            out[0] = (float)(a0 / (double)N_REC + 0.25 * mem - 0.1 * a2 / (double)N_DHAT);
            g_acc[0] = 0.0; g_acc[1] = 0.0; g_acc[2] = 0.0; g_acc[3] = 0.0;
            g_ticket = 0u; g_mready = 0u;
            __threadfence();
        }
    }
}

extern "C" void kernel_launch(void* const* d_in, const int* in_sizes, int n_in,
                              void* d_out, int out_size) {
    (void)in_sizes; (void)n_in; (void)out_size;
    const float* Xhat = (const float*)d_in[0];
    const float* X    = (const float*)d_in[1];
    const float* H    = (const float*)d_in[2];
    const float* M    = (const float*)d_in[3];
    const float* Dh   = (const float*)d_in[4];

    cudaFuncSetAttribute(k_fused, cudaFuncAttributeMaxDynamicSharedMemorySize, SMEMT);

    k_fused<<<148, 256, SMEMT>>>(H, M, Xhat, X, Dh, (float*)d_out);
}

// round 17
// speedup vs baseline: 1.1296x; 1.0172x over previous
#include <cuda_runtime.h>
#include <cuda_bf16.h>
#include <cstdint>

// EDMLoss = mean((Xhat-X)^2) + 0.25*memloss - 0.1*mean(Dhat)
// memloss = 2*(sum||h||^2 + sum_row min_k(||m_k||^2 - 2 h.m_k)) / (B*D*T)
// SINGLE LAUNCH. 148 CTAs:
//   0..127  : GEMM CTAs (256 rows x 512 cols, mma.sync bf16 at the legacy-path
//             ceiling ~512 MAC/cyc/SM). A-stage first, then wait for M-ready.
//   128..143: convert M->bf16 + ||m||^2 (32 k-cols each), signal, then rec slices.
//   144..145: rec slices.   146..147: dhat slices.
// Ticketed finalize; all globals reset each run (graph-replay invariant).
// [Final: best measured config, R14. 374.8us baseline -> 35.5us (10.6x).]

namespace {
constexpr int Bn = 64, Dn = 256, Tn = 512, Kn = 512;
constexpr int N_REC  = 64 * 8 * 512;
constexpr int N_DHAT = 64 * 512;

constexpr uint32_t AP    = 528;                 // A pitch bytes (256 bf16 + 16 pad)
constexpr uint32_t BP    = 144;                 // B pitch bytes (64 bf16 + 16 pad)
constexpr uint32_t SA    = 0;                   // A: 256*528 = 135168
constexpr uint32_t SB0   = 135168;              // B buf0: 256*144 = 36864
constexpr uint32_t SB1   = 172032;              // B buf1
constexpr uint32_t SMNS  = 208896;              // 512 f32 ||m||^2
constexpr uint32_t SRMIN = 210944;              // 2 groups * 256 f32 row mins
constexpr uint32_t SRED  = 212992;              // 8 f32 | 8 doubles at +64
constexpr uint32_t SMEMT = 213120;
}

__device__ double g_acc[4];      // 0 rec, 1 minscore, 2 dhat, 3 sum H^2 (zero-invariant)
__device__ unsigned g_ticket;
__device__ unsigned g_mready;    // 16 converter CTAs arrive; reset by finalize
__device__ float  g_mnorm[Kn];
__device__ __align__(16) __nv_bfloat16 g_Mc[(size_t)Dn * Kn];

__device__ __forceinline__ uint32_t smem_u32(const void* p) {
    uint32_t a;
    asm("{ .reg .u64 t; cvta.to.shared.u64 t, %1; cvt.u32.u64 %0, t; }" : "=r"(a) : "l"(p));
    return a;
}
__device__ __forceinline__ void ldsm4t(uint32_t* r, uint32_t addr) {
    asm volatile("ldmatrix.sync.aligned.m8n8.x4.trans.shared.b16 {%0,%1,%2,%3}, [%4];"
                 : "=r"(r[0]), "=r"(r[1]), "=r"(r[2]), "=r"(r[3]) : "r"(addr));
}
__device__ __forceinline__ void mma16816(float* c, const uint32_t* a, const uint32_t* b) {
    asm volatile("mma.sync.aligned.m16n8k16.row.col.f32.bf16.bf16.f32 "
                 "{%0,%1,%2,%3}, {%4,%5,%6,%7}, {%8,%9}, {%0,%1,%2,%3};"
                 : "+f"(c[0]), "+f"(c[1]), "+f"(c[2]), "+f"(c[3])
                 : "r"(a[0]), "r"(a[1]), "r"(a[2]), "r"(a[3]), "r"(b[0]), "r"(b[1]));
}

__global__ __launch_bounds__(256, 1) void k_fused(const float* __restrict__ H,
                                                  const float* __restrict__ M,
                                                  const float* __restrict__ Xhat,
                                                  const float* __restrict__ X,
                                                  const float* __restrict__ Dh,
                                                  float* out) {
    extern __shared__ char sm[];
    const uint32_t sb = smem_u32(sm);
    const int tid = threadIdx.x, w = tid >> 5, ln = tid & 31;

    if (blockIdx.x >= 128) {
        // -------- converter / reduction CTAs --------
        if (blockIdx.x < 144) {
            // convert 32 k-cols of M -> bf16, compute ||m||^2, signal ready
            __shared__ float part[8][32];
            const int kl = tid & 31, dg = tid >> 5;
            const int k  = ((int)blockIdx.x - 128) * 32 + kl;
            float s = 0.f;
            #pragma unroll 8
            for (int i = 0; i < 32; ++i) {
                int d = dg * 32 + i;
                float v = M[(size_t)d * Kn + k];
                g_Mc[(size_t)d * Kn + k] = __float2bfloat16(v);
                s = fmaf(v, v, s);
            }
            part[dg][kl] = s;
            __syncthreads();
            if (dg == 0) {
                float t = 0.f;
                #pragma unroll
                for (int i = 0; i < 8; ++i) t += part[i][kl];
                g_mnorm[k] = t;
            }
            __syncthreads();
            __threadfence();
            if (tid == 0) atomicAdd(&g_mready, 1u);
        }
        // rec / dhat slices
        int which, n, b0, nb;
        const float* a; const float* bp;
        if (blockIdx.x < 146) { which = 0; a = Xhat; bp = X; n = N_REC;  b0 = 128; nb = 18; }
        else                  { which = 2; a = Dh;   bp = 0; n = N_DHAT; b0 = 146; nb = 2;  }
        float s = 0.f;
        for (int i = ((int)blockIdx.x - b0) * 256 + tid; i < n; i += nb * 256) {
            if (which == 0) { float d = a[i] - bp[i]; s = fmaf(d, d, s); }
            else            { s += a[i]; }
        }
        #pragma unroll
        for (int o = 16; o; o >>= 1) s += __shfl_down_sync(0xffffffffu, s, o);
        float* ws = (float*)(sm + SRED);
        if (!ln) ws[w] = s;
        __syncthreads();
        if (tid == 0) {
            float t = 0.f;
            #pragma unroll
            for (int i = 0; i < 8; ++i) t += ws[i];
            atomicAdd(&g_acc[which], (double)t);
        }
    } else {
        // -------- GEMM CTA: 256 rows x 512 cols --------
        const int row0 = blockIdx.x * 256;
        const int b = row0 >> 9, t0 = row0 & 511;          // t0 in {0, 256}

        // Stage A FIRST (independent of M): H fp32 -> bf16 smem [d][t] + sum(H^2).
        float sq = 0.f;
        const float* Hp = H + (size_t)b * Dn * Tn + t0;
        #pragma unroll
        for (int i = 0; i < 64; ++i) {
            int u = tid + 256 * i;                 // 0..16383 float4 units
            int d = u >> 6, seg = u & 63;
            float4 v = *(const float4*)(Hp + (size_t)d * Tn + seg * 4);
            sq = fmaf(v.x, v.x, fmaf(v.y, v.y, fmaf(v.z, v.z, fmaf(v.w, v.w, sq))));
            __nv_bfloat162 p0 = __floats2bfloat162_rn(v.x, v.y);
            __nv_bfloat162 p1 = __floats2bfloat162_rn(v.z, v.w);
            uint32_t a = sb + SA + d * AP + seg * 8;
            asm volatile("st.shared.v2.b32 [%0], {%1,%2};"
                         :: "r"(a), "r"(*(uint32_t*)&p0), "r"(*(uint32_t*)&p1) : "memory");
        }
        #pragma unroll
        for (int o = 16; o; o >>= 1) sq += __shfl_down_sync(0xffffffffu, sq, o);
        if (!ln) ((float*)(sm + SRED))[w] = sq;
        __syncthreads();
        if (tid == 0) {
            const float* hws = (const float*)(sm + SRED);
            double hs = 0.0;
            #pragma unroll
            for (int i = 0; i < 8; ++i) hs += (double)hws[i];
            atomicAdd(&g_acc[3], hs);
            // wait for M conversion (usually done long ago: conversion ~1us vs A-stage ~5us)
            while (*((volatile unsigned*)&g_mready) < 16u) __nanosleep(64);
        }
        __syncthreads();
        __threadfence();

        ((float*)(sm + SMNS))[tid]       = g_mnorm[tid];
        ((float*)(sm + SMNS))[tid + 256] = g_mnorm[tid + 256];

        const size_t gmc = __cvta_generic_to_global((const void*)g_Mc);
        auto cp_chunk = [&](int c, uint32_t dstoff) {       // 64-col chunk: 256 rows * 128B
            #pragma unroll
            for (int i = 0; i < 8; ++i) {
                int u = tid + 256 * i;                      // 0..2047 16B units
                int d = u >> 3, seg = u & 7;
                uint32_t dst = sb + dstoff + d * BP + seg * 16;
                size_t   src = gmc + (size_t)d * 1024 + (size_t)c * 128 + seg * 16;
                asm volatile("cp.async.cg.shared.global [%0], [%1], 16;" :: "r"(dst), "l"(src));
            }
            asm volatile("cp.async.commit_group;" ::: "memory");
        };
        cp_chunk(0, SB0);
        cp_chunk(1, SB1);

        // 8 warps: 4 (m) x 2 (n). Warp tile per chunk: 64 rows x 32 cols.
        const int wm  = (w & 3) * 64;
        const int wn  = (w >> 2) * 32;
        const int s1  = ((ln >> 3) & 1) * 8;
        const int s2  = (ln >> 4) * 8;
        const int r8  = ln & 7;
        const float* mns = (const float*)(sm + SMNS);

        float rm[8];
        #pragma unroll
        for (int i = 0; i < 8; ++i) rm[i] = 3.4e38f;

        // Single barrier per chunk: sync proves chunk c arrived AND chunk c-1
        // consumers finished -> buffer (c+1)&1 free; prefetch immediately.
        for (int c = 0; c < 8; ++c) {
            if (c == 0) asm volatile("cp.async.wait_group 1;" ::: "memory");
            else        asm volatile("cp.async.wait_group 0;" ::: "memory");
            __syncthreads();
            if (c >= 1 && c + 1 < 8) cp_chunk(c + 1, ((c + 1) & 1) ? SB1 : SB0);
            const uint32_t bb = sb + ((c & 1) ? SB1 : SB0);

            float acc[4][4][4];
            #pragma unroll
            for (int mf = 0; mf < 4; ++mf)
                #pragma unroll
                for (int nf = 0; nf < 4; ++nf)
                    #pragma unroll
                    for (int j = 0; j < 4; ++j) acc[mf][nf][j] = 0.f;

            #pragma unroll
            for (int ks = 0; ks < 16; ++ks) {
                const int d0 = ks * 16;
                uint32_t af[4][4], bf[2][4];
                #pragma unroll
                for (int np = 0; np < 2; ++np)
                    ldsm4t(bf[np], bb + (d0 + s1 + r8) * BP + (wn + np * 16 + s2) * 2);
                #pragma unroll
                for (int mf = 0; mf < 4; ++mf)
                    ldsm4t(af[mf], sb + SA + (d0 + s2 + r8) * AP + (wm + mf * 16 + s1) * 2);
                #pragma unroll
                for (int mf = 0; mf < 4; ++mf)
                    #pragma unroll
                    for (int nf = 0; nf < 4; ++nf)
                        mma16816(acc[mf][nf], af[mf], &bf[nf >> 1][(nf & 1) * 2]);
            }

            // epilogue: score = ||m||^2 - 2*dot, running min per row
            const int cb = c * 64 + wn + 2 * (ln & 3);
            #pragma unroll
            for (int nf = 0; nf < 4; ++nf) {
                float m0 = mns[cb + nf * 8], m1 = mns[cb + nf * 8 + 1];
                #pragma unroll
                for (int mf = 0; mf < 4; ++mf) {
                    rm[mf * 2]     = fminf(rm[mf * 2],
                        fminf(fmaf(-2.f, acc[mf][nf][0], m0), fmaf(-2.f, acc[mf][nf][1], m1)));
                    rm[mf * 2 + 1] = fminf(rm[mf * 2 + 1],
                        fminf(fmaf(-2.f, acc[mf][nf][2], m0), fmaf(-2.f, acc[mf][nf][3], m1)));
                }
            }
        }

        // combine 4 lanes sharing each row
        #pragma unroll
        for (int o = 1; o < 4; o <<= 1) {
            #pragma unroll
            for (int i = 0; i < 8; ++i) rm[i] = fminf(rm[i], __shfl_xor_sync(0xffffffffu, rm[i], o));
        }
        if ((ln & 3) == 0) {
            float* rmin = (float*)(sm + SRMIN) + (w >> 2) * 256;
            int r = wm + (ln >> 2);
            #pragma unroll
            for (int mf = 0; mf < 4; ++mf) {
                rmin[r + mf * 16]     = rm[mf * 2];
                rmin[r + mf * 16 + 8] = rm[mf * 2 + 1];
            }
        }
        __syncthreads();

        {   // combine n-groups, sum rows
            const float* r0 = (const float*)(sm + SRMIN);
            double s = (double)fminf(r0[tid], r0[tid + 256]);
            #pragma unroll
            for (int o = 16; o; o >>= 1) s += __shfl_down_sync(0xffffffffu, s, o);
            if (!ln) ((double*)(sm + SRED + 64))[w] = s;
        }
        __syncthreads();

        if (tid == 0) {
            const double* dr = (const double*)(sm + SRED + 64);
            double ms = 0.0;
            #pragma unroll
            for (int i = 0; i < 8; ++i) ms += dr[i];
            atomicAdd(&g_acc[1], ms);
        }
    }

    // -------- shared ticketed finalize (all 148 CTAs) --------
    if (tid == 0) {
        __threadfence();
        unsigned old = atomicAdd(&g_ticket, 1u);
        if (old == gridDim.x - 1) {
            __threadfence();
            double a0 = *(volatile double*)&g_acc[0];
            double a1 = *(volatile double*)&g_acc[1];
            double a2 = *(volatile double*)&g_acc[2];
            double a3 = *(volatile double*)&g_acc[3];
            double mem = 2.0 * (a3 + a1) / (double)((size_t)Bn * Dn * Tn);
            out[0] = (float)(a0 / (double)N_REC + 0.25 * mem - 0.1 * a2 / (double)N_DHAT);
            g_acc[0] = 0.0; g_acc[1] = 0.0; g_acc[2] = 0.0; g_acc[3] = 0.0;
            g_ticket = 0u; g_mready = 0u;
            __threadfence();
        }
    }
}

extern "C" void kernel_launch(void* const* d_in, const int* in_sizes, int n_in,
                              void* d_out, int out_size) {
    (void)in_sizes; (void)n_in; (void)out_size;
    const float* Xhat = (const float*)d_in[0];
    const float* X    = (const float*)d_in[1];
    const float* H    = (const float*)d_in[2];
    const float* M    = (const float*)d_in[3];
    const float* Dh   = (const float*)d_in[4];

    cudaFuncSetAttribute(k_fused, cudaFuncAttributeMaxDynamicSharedMemorySize, SMEMT);

    k_fused<<<148, 256, SMEMT>>>(H, M, Xhat, X, Dh, (float*)d_out);
}